// round 14
// baseline (speedup 1.0000x reference)
#include <cuda_runtime.h>

#define NF 36
#define NO 1000
#define NT 256
#define NC 81

// Raw MUFU.RCP (~2^-21 rel err) — explicitly approx regardless of host flags.
__device__ __forceinline__ float rcp_approx(float x) {
    float r;
    asm("rcp.approx.f32 %0, %1;" : "=f"(r) : "f"(x));
    return r;
}

// ---------------------------------------------------------------------------
// A) Fused softmax + class cost. Block owns 2 o's x 256 t, 512 threads:
//    16 warps share the 72 softmax rows; gather split across thread halves.
//    Initializes d_out with class term + GIoU "+1" constant.
//    Triggers programmatic launch completion immediately so box_kernel
//    co-schedules onto idle slots.
// ---------------------------------------------------------------------------
__global__ __launch_bounds__(512) void class_kernel(
    const float* __restrict__ logits,  // [F*O, C]
    const int*   __restrict__ tgt_ids, // [T*F]
    float*       __restrict__ out)     // [O, T]
{
    if (threadIdx.x == 0) cudaTriggerProgrammaticLaunchCompletion();

    __shared__ float2 s_prob2[NF][NC];        // 23328 B
    __shared__ int    s_id4[NT][NF / 4];      // 9216 B
    __shared__ float2 s_part[NT];             // 2048 B

    const int ob   = blockIdx.x * 2;
    const int tid  = threadIdx.x;
    const int warp = tid >> 5;                // 0..15
    const int lane = tid & 31;

    // ---- batch-load this warp's rows (up to 5 of 72; 15 LDGs in flight) ----
    float v[5][3];
    float s[5];
    #pragma unroll
    for (int k = 0; k < 5; k++) {
        int r = warp + 16 * k;                // 0..79, valid < 72
        if (r < 2 * NF) {
            int ol = r / NF;
            int f  = r - ol * NF;
            const float* in = logits + (size_t)(f * NO + ob + ol) * NC;
            v[k][0] = in[lane];
            v[k][1] = in[lane + 32];
            v[k][2] = (lane < 17) ? in[lane + 64] : 0.0f;
        } else {
            v[k][0] = v[k][1] = v[k][2] = 0.0f;
        }
    }

    // ---- exp (max-free: logits are O(1)) + per-row partial sums ----
    #pragma unroll
    for (int k = 0; k < 5; k++) {
        float e0 = __expf(v[k][0]);
        float e1 = __expf(v[k][1]);
        float e2 = (lane < 17) ? __expf(v[k][2]) : 0.0f;
        v[k][0] = e0; v[k][1] = e1; v[k][2] = e2;
        s[k] = e0 + e1 + e2;
    }

    // ---- 5 independent SHFL chains, interleaved ----
    #pragma unroll
    for (int st = 16; st; st >>= 1) {
        #pragma unroll
        for (int k = 0; k < 5; k++)
            s[k] += __shfl_xor_sync(0xffffffffu, s[k], st);
    }

    // ---- normalize straight into interleaved SMEM ----
    #pragma unroll
    for (int k = 0; k < 5; k++) {
        int r = warp + 16 * k;
        if (r < 2 * NF) {
            float inv = rcp_approx(s[k]);
            int ol = r / NF;
            int f  = r - ol * NF;
            float* dst = (float*)&s_prob2[f][0] + ol;   // stride-2 interleave
            dst[2 * lane]        = v[k][0] * inv;
            dst[2 * (lane + 32)] = v[k][1] * inv;
            if (lane < 17) dst[2 * (lane + 64)] = v[k][2] * inv;
        }
    }

    // ---- pack ids: 4 consecutive frames per int ----
    const int4* ids4 = (const int4*)tgt_ids;
    for (int i = tid; i < NT * NF / 4; i += 512) {
        int4 q = ids4[i];
        int t = i / (NF / 4);
        int p = i - t * (NF / 4);
        s_id4[t][p] = (q.x) | (q.y << 8) | (q.z << 16) | (q.w << 24);
    }
    __syncthreads();

    // ---- gather, split across thread halves: fq 0..3 / fq 4..8 ----
    const int t    = tid & (NT - 1);
    const int half = tid >> 8;          // 0 or 1
    const int fq0  = half ? 4 : 0;
    const int fq1  = half ? 9 : 4;

    float a0 = 0.0f, a1 = 0.0f;
    #pragma unroll
    for (int fq = fq0; fq < fq1; fq++) {
        int packed = s_id4[t][fq];
        #pragma unroll
        for (int b = 0; b < 4; b++) {
            int c = (packed >> (8 * b)) & 0xFF;
            float2 pr = s_prob2[fq * 4 + b][c];
            a0 += pr.x;
            a1 += pr.y;
        }
    }
    if (half) s_part[t] = make_float2(a0, a1);
    __syncthreads();
    if (!half) {
        float2 p = s_part[t];
        a0 += p.x;
        a1 += p.y;
        out[(ob + 0) * NT + t] = 1.0f - a0 * (1.0f / NF);
        out[(ob + 1) * NT + t] = 1.0f - a1 * (1.0f / NF);
    }
}

// ---------------------------------------------------------------------------
// B) Box cost: 16 o x 16 t tiles, warp = 16t x 2o (adjacent lanes share t),
//    xyxy-only smem, manual prefetch. GIoU rational term via ONE approx
//    reciprocal (raw MUFU.RCP, no IEEE refinement sequence).
//    PDL: compute overlaps class_kernel; gridDependencySynchronize gates
//    only the final += on out.
// ---------------------------------------------------------------------------
__global__ __launch_bounds__(256) void box_kernel(
    const float4* __restrict__ pred_boxes,   // [F, O] cxcywh
    const float4* __restrict__ tgt_bbox,     // [T, F] cxcywh
    float*        __restrict__ out)          // [O, T]
{
    __shared__ float4 s_pred[16][NF];    // xyxy 9216 B
    __shared__ float4 s_tgt[NF][16];     // xyxy 9216 B

    const int ob  = blockIdx.y * 16;
    const int tb  = blockIdx.x * 16;
    const int tid = threadIdx.x;

    for (int i = tid; i < 16 * NF; i += 256) {
        int ol = i & 15, f = i >> 4;
        int o  = min(ob + ol, NO - 1);            // clamp ragged last o-tile
        float4 b = pred_boxes[f * NO + o];
        s_pred[ol][f] = make_float4(b.x - 0.5f * b.z, b.y - 0.5f * b.w,
                                    b.x + 0.5f * b.z, b.y + 0.5f * b.w);
    }
    for (int i = tid; i < 16 * NF; i += 256) {
        int tl = i / NF, f = i - tl * NF;
        float4 b = tgt_bbox[(tb + tl) * NF + f];
        s_tgt[f][tl] = make_float4(b.x - 0.5f * b.z, b.y - 0.5f * b.w,
                                   b.x + 0.5f * b.z, b.y + 0.5f * b.w);
    }
    __syncthreads();

    const int lane = tid & 31;
    const int wid  = tid >> 5;
    const int op   = lane & 1;        // which of the warp's 2 o's
    const int tl   = lane >> 1;       // t within tile (adjacent lanes share)
    const int ol   = 2 * wid + op;    // o within tile

    float accG = 0.0f;   // sum over f of (inter/uni + uni/ca) == giou + 1
    float accC = 0.0f;   // |dx0+dx1| + |dy0+dy1|  (center terms, x2 scale)
    float accW = 0.0f;   // |dx1-dx0| + |dy1-dy0|  (w/h terms)

    float4 P = s_pred[ol][0];
    float4 T = s_tgt[0][tl];

    #pragma unroll 4
    for (int f = 0; f < NF; f++) {
        float4 Pn, Tn;
        if (f < NF - 1) {                 // prefetch next frame
            Pn = s_pred[ol][f + 1];
            Tn = s_tgt[f + 1][tl];
        }

        float pw = P.z - P.x, ph = P.w - P.y;
        float tw = T.z - T.x, th = T.w - T.y;

        float iw = fminf(P.z, T.z) - fmaxf(P.x, T.x);
        float ih = fminf(P.w, T.w) - fmaxf(P.y, T.y);
        float inter = fmaxf(iw, 0.0f) * fmaxf(ih, 0.0f);
        float uni = fmaf(pw, ph, tw * th) - inter;
        float ca  = ((pw + tw) - iw) * ((ph + th) - ih);

        // inter/uni + uni/ca = (inter*ca + uni*uni) / (uni*ca), ONE MUFU.RCP
        float r = rcp_approx(uni * ca);
        accG = fmaf(fmaf(inter, ca, uni * uni), r, accG);

        float dx0 = P.x - T.x, dx1 = P.z - T.z;
        float dy0 = P.y - T.y, dy1 = P.w - T.w;
        accC += fabsf(dx0 + dx1) + fabsf(dy0 + dy1);
        accW += fabsf(dx1 - dx0) + fabsf(dy1 - dy0);

        P = Pn; T = Tn;
    }

    // Wait for class_kernel's writes to `out` to be visible, then accumulate.
    cudaGridDependencySynchronize();

    int o = ob + ol;
    int t = tb + tl;
    if (o < NO) {
        // bbox = (0.5*accC + accW)/(NF*4); giou "+1" folded into class init.
        out[o * NT + t] += (0.5f * accC + accW) * (1.0f / (NF * 4))
                           - accG * (1.0f / NF);
    }
}

// ---------------------------------------------------------------------------
extern "C" void kernel_launch(void* const* d_in, const int* in_sizes, int n_in,
                              void* d_out, int out_size) {
    const float* pred_logits = (const float*)d_in[0];
    const float* pred_boxes  = (const float*)d_in[1];
    const float* tgt_bbox    = (const float*)d_in[2];
    const int*   tgt_ids     = (const int*)d_in[3];
    float* out = (float*)d_out;

    class_kernel<<<NO / 2, 512>>>(pred_logits, tgt_ids, out);

    // Box kernel with Programmatic Dependent Launch: starts while class_kernel
    // is still running; its gridDependencySynchronize orders the out += .
    cudaLaunchConfig_t cfg = {};
    cfg.gridDim  = dim3(NT / 16, (NO + 15) / 16, 1);
    cfg.blockDim = dim3(256, 1, 1);
    cfg.dynamicSmemBytes = 0;
    cfg.stream = 0;
    cudaLaunchAttribute attr[1];
    attr[0].id = cudaLaunchAttributeProgrammaticStreamSerialization;
    attr[0].val.programmaticStreamSerializationAllowed = 1;
    cfg.attrs = attr;
    cfg.numAttrs = 1;
    cudaLaunchKernelEx(&cfg, box_kernel,
                       (const float4*)pred_boxes, (const float4*)tgt_bbox, out);
}

// round 15
// speedup vs baseline: 1.0828x; 1.0828x over previous
#include <cuda_runtime.h>

#define NF 36
#define NO 1000
#define NT 256
#define NC 81

// Raw MUFU.RCP (~2^-21 rel err) — explicitly approx regardless of host flags.
__device__ __forceinline__ float rcp_approx(float x) {
    float r;
    asm("rcp.approx.f32 %0, %1;" : "=f"(r) : "f"(x));
    return r;
}

// ---------------------------------------------------------------------------
// A) Fused softmax + class cost. Block owns 2 o's x 256 t, 512 threads.
//    Initializes d_out with class term + GIoU "+1" constant. PDL trigger at
//    start so box_kernel co-schedules onto idle slots.
// ---------------------------------------------------------------------------
__global__ __launch_bounds__(512) void class_kernel(
    const float* __restrict__ logits,  // [F*O, C]
    const int*   __restrict__ tgt_ids, // [T*F]
    float*       __restrict__ out)     // [O, T]
{
    if (threadIdx.x == 0) cudaTriggerProgrammaticLaunchCompletion();

    __shared__ float2 s_prob2[NF][NC];        // 23328 B
    __shared__ int    s_id4[NT][NF / 4];      // 9216 B
    __shared__ float2 s_part[NT];             // 2048 B

    const int ob   = blockIdx.x * 2;
    const int tid  = threadIdx.x;
    const int warp = tid >> 5;                // 0..15
    const int lane = tid & 31;

    // ---- batch-load this warp's rows (up to 5 of 72; 15 LDGs in flight) ----
    float v[5][3];
    float s[5];
    #pragma unroll
    for (int k = 0; k < 5; k++) {
        int r = warp + 16 * k;                // 0..79, valid < 72
        if (r < 2 * NF) {
            int ol = r / NF;
            int f  = r - ol * NF;
            const float* in = logits + (size_t)(f * NO + ob + ol) * NC;
            v[k][0] = in[lane];
            v[k][1] = in[lane + 32];
            v[k][2] = (lane < 17) ? in[lane + 64] : 0.0f;
        } else {
            v[k][0] = v[k][1] = v[k][2] = 0.0f;
        }
    }

    // ---- exp (max-free: logits are O(1)) + per-row partial sums ----
    #pragma unroll
    for (int k = 0; k < 5; k++) {
        float e0 = __expf(v[k][0]);
        float e1 = __expf(v[k][1]);
        float e2 = (lane < 17) ? __expf(v[k][2]) : 0.0f;
        v[k][0] = e0; v[k][1] = e1; v[k][2] = e2;
        s[k] = e0 + e1 + e2;
    }

    // ---- 5 independent SHFL chains, interleaved ----
    #pragma unroll
    for (int st = 16; st; st >>= 1) {
        #pragma unroll
        for (int k = 0; k < 5; k++)
            s[k] += __shfl_xor_sync(0xffffffffu, s[k], st);
    }

    // ---- normalize straight into interleaved SMEM ----
    #pragma unroll
    for (int k = 0; k < 5; k++) {
        int r = warp + 16 * k;
        if (r < 2 * NF) {
            float inv = rcp_approx(s[k]);
            int ol = r / NF;
            int f  = r - ol * NF;
            float* dst = (float*)&s_prob2[f][0] + ol;   // stride-2 interleave
            dst[2 * lane]        = v[k][0] * inv;
            dst[2 * (lane + 32)] = v[k][1] * inv;
            if (lane < 17) dst[2 * (lane + 64)] = v[k][2] * inv;
        }
    }

    // ---- pack ids: 4 consecutive frames per int ----
    const int4* ids4 = (const int4*)tgt_ids;
    for (int i = tid; i < NT * NF / 4; i += 512) {
        int4 q = ids4[i];
        int t = i / (NF / 4);
        int p = i - t * (NF / 4);
        s_id4[t][p] = (q.x) | (q.y << 8) | (q.z << 16) | (q.w << 24);
    }
    __syncthreads();

    // ---- gather, split across thread halves: fq 0..3 / fq 4..8 ----
    const int t    = tid & (NT - 1);
    const int half = tid >> 8;          // 0 or 1
    const int fq0  = half ? 4 : 0;
    const int fq1  = half ? 9 : 4;

    float a0 = 0.0f, a1 = 0.0f;
    #pragma unroll
    for (int fq = fq0; fq < fq1; fq++) {
        int packed = s_id4[t][fq];
        #pragma unroll
        for (int b = 0; b < 4; b++) {
            int c = (packed >> (8 * b)) & 0xFF;
            float2 pr = s_prob2[fq * 4 + b][c];
            a0 += pr.x;
            a1 += pr.y;
        }
    }
    if (half) s_part[t] = make_float2(a0, a1);
    __syncthreads();
    if (!half) {
        float2 p = s_part[t];
        a0 += p.x;
        a1 += p.y;
        out[(ob + 0) * NT + t] = 1.0f - a0 * (1.0f / NF);
        out[(ob + 1) * NT + t] = 1.0f - a1 * (1.0f / NF);
    }
}

// ---------------------------------------------------------------------------
// B) Box cost: 16 o x 16 t tiles, warp = 16t x 2o (adjacent lanes share t),
//    xyxy-only smem. F-LOOP FULLY UNROLLED: every LDS gets an immediate
//    offset (no address arithmetic), no loop control, ptxas schedules the
//    loads ahead itself. One approx reciprocal per pair-frame.
//    PDL: gridDependencySynchronize gates only the final += on out.
// ---------------------------------------------------------------------------
__global__ __launch_bounds__(256) void box_kernel(
    const float4* __restrict__ pred_boxes,   // [F, O] cxcywh
    const float4* __restrict__ tgt_bbox,     // [T, F] cxcywh
    float*        __restrict__ out)          // [O, T]
{
    __shared__ float4 s_pred[16][NF];    // xyxy 9216 B
    __shared__ float4 s_tgt[NF][16];     // xyxy 9216 B

    const int ob  = blockIdx.y * 16;
    const int tb  = blockIdx.x * 16;
    const int tid = threadIdx.x;

    for (int i = tid; i < 16 * NF; i += 256) {
        int ol = i & 15, f = i >> 4;
        int o  = min(ob + ol, NO - 1);            // clamp ragged last o-tile
        float4 b = pred_boxes[f * NO + o];
        s_pred[ol][f] = make_float4(b.x - 0.5f * b.z, b.y - 0.5f * b.w,
                                    b.x + 0.5f * b.z, b.y + 0.5f * b.w);
    }
    for (int i = tid; i < 16 * NF; i += 256) {
        int tl = i / NF, f = i - tl * NF;
        float4 b = tgt_bbox[(tb + tl) * NF + f];
        s_tgt[f][tl] = make_float4(b.x - 0.5f * b.z, b.y - 0.5f * b.w,
                                   b.x + 0.5f * b.z, b.y + 0.5f * b.w);
    }
    __syncthreads();

    const int lane = tid & 31;
    const int wid  = tid >> 5;
    const int op   = lane & 1;        // which of the warp's 2 o's
    const int tl   = lane >> 1;       // t within tile (adjacent lanes share)
    const int ol   = 2 * wid + op;    // o within tile

    // base pointers; f-indexed accesses below have compile-time offsets
    const float4* __restrict__ Pbase = &s_pred[ol][0];   // stride 16 B per f
    const float4* __restrict__ Tbase = &s_tgt[0][tl];    // stride 256 B per f

    float accG = 0.0f;   // sum over f of (inter/uni + uni/ca) == giou + 1
    float accC = 0.0f;   // |dx0+dx1| + |dy0+dy1|  (center terms, x2 scale)
    float accW = 0.0f;   // |dx1-dx0| + |dy1-dy0|  (w/h terms)

    #pragma unroll
    for (int f = 0; f < NF; f++) {
        float4 P = Pbase[f];          // LDS.128, immediate offset f*16
        float4 T = Tbase[f * 16];     // LDS.128, immediate offset f*256

        float pw = P.z - P.x, ph = P.w - P.y;
        float tw = T.z - T.x, th = T.w - T.y;

        float iw = fminf(P.z, T.z) - fmaxf(P.x, T.x);
        float ih = fminf(P.w, T.w) - fmaxf(P.y, T.y);
        float inter = fmaxf(iw, 0.0f) * fmaxf(ih, 0.0f);
        float uni = fmaf(pw, ph, tw * th) - inter;
        float ca  = ((pw + tw) - iw) * ((ph + th) - ih);

        // inter/uni + uni/ca = (inter*ca + uni*uni) / (uni*ca), ONE MUFU.RCP
        float r = rcp_approx(uni * ca);
        accG = fmaf(fmaf(inter, ca, uni * uni), r, accG);

        float dx0 = P.x - T.x, dx1 = P.z - T.z;
        float dy0 = P.y - T.y, dy1 = P.w - T.w;
        accC += fabsf(dx0 + dx1) + fabsf(dy0 + dy1);
        accW += fabsf(dx1 - dx0) + fabsf(dy1 - dy0);
    }

    // Wait for class_kernel's writes to `out` to be visible, then accumulate.
    cudaGridDependencySynchronize();

    int o = ob + ol;
    int t = tb + tl;
    if (o < NO) {
        // bbox = (0.5*accC + accW)/(NF*4); giou "+1" folded into class init.
        out[o * NT + t] += (0.5f * accC + accW) * (1.0f / (NF * 4))
                           - accG * (1.0f / NF);
    }
}

// ---------------------------------------------------------------------------
extern "C" void kernel_launch(void* const* d_in, const int* in_sizes, int n_in,
                              void* d_out, int out_size) {
    const float* pred_logits = (const float*)d_in[0];
    const float* pred_boxes  = (const float*)d_in[1];
    const float* tgt_bbox    = (const float*)d_in[2];
    const int*   tgt_ids     = (const int*)d_in[3];
    float* out = (float*)d_out;

    class_kernel<<<NO / 2, 512>>>(pred_logits, tgt_ids, out);

    // Box kernel with Programmatic Dependent Launch: starts while class_kernel
    // is still running; its gridDependencySynchronize orders the out += .
    cudaLaunchConfig_t cfg = {};
    cfg.gridDim  = dim3(NT / 16, (NO + 15) / 16, 1);
    cfg.blockDim = dim3(256, 1, 1);
    cfg.dynamicSmemBytes = 0;
    cfg.stream = 0;
    cudaLaunchAttribute attr[1];
    attr[0].id = cudaLaunchAttributeProgrammaticStreamSerialization;
    attr[0].val.programmaticStreamSerializationAllowed = 1;
    cfg.attrs = attr;
    cfg.numAttrs = 1;
    cudaLaunchKernelEx(&cfg, box_kernel,
                       (const float4*)pred_boxes, (const float4*)tgt_bbox, out);
}